// round 6
// baseline (speedup 1.0000x reference)
#include <cuda_runtime.h>
#include <cuda_bf16.h>
#include <math.h>
#include <stdint.h>

#define N_NODES 100000
#define N_EDGES 100000
#define NNZ_MAX 1600000
#define C 128

// ---- scratch (device globals; allocation-free per harness rules) -----------
__device__ __align__(16) float g_T[(size_t)N_NODES * C];  // node-pass output (51.2MB)
__device__ __align__(16) float g_M[(size_t)N_EDGES * C];  // per-edge m rows (51.2MB)
__device__ float g_ns[N_NODES];                           // x0 @ a_tgt
__device__ float g_es[N_EDGES];                           // m @ a_src
__device__ int   g_rowptr[N_EDGES + 1];
__device__ int   g_nodeptr[N_NODES + 1];
__device__ int   g_pos[N_NODES];
__device__ int   g_cnt[N_NODES];
__device__ int   g_node[NNZ_MAX];
__device__ int   g_edge[NNZ_MAX];
__device__ float g_val[NNZ_MAX];
__device__ int   g_pe[NNZ_MAX];     // edge id, sorted by node
__device__ float g_pv[NNZ_MAX];    // value, sorted by node
__device__ int   g_is64;
__device__ int   g_rolemap[3];
// W^T pair-packed bf16 hi/lo: g_Wh[n*64 + kp] = {W[2kp][n], W[2kp+1][n]}
__device__ __align__(16) unsigned g_Wh[C * C / 2];
__device__ __align__(16) unsigned g_Wl[C * C / 2];

// ---- detect dtype (int32 vs int64) and buffer roles on-device --------------
__global__ void detect_kernel(const unsigned* __restrict__ b0,
                              const unsigned* __restrict__ b1,
                              const unsigned* __restrict__ b2, int nnz) {
    __shared__ int s_float[3], s_oddzero[3], s_sorted[3], s_is64;
    __shared__ unsigned s_vals[3][64];
    int t = threadIdx.x;
    int b = t >> 6, k = t & 63;
    const unsigned* bufs[3] = {b0, b1, b2};
    if (t < 3) { s_float[t] = 1; s_oddzero[t] = 1; s_sorted[t] = 1; }
    __syncthreads();

    const unsigned* p = bufs[b];
    unsigned q = (unsigned)(((long long)k * (nnz - 2)) / 63);
    unsigned w_even = p[q & ~1u];
    unsigned w_odd  = p[q | 1u];
    if (w_even <= 0x01000000u) atomicAnd(&s_float[b], 0);
    if (w_odd != 0u)           atomicAnd(&s_oddzero[b], 0);
    __syncthreads();

    if (t == 0) {
        int is64 = 1;
        for (int i = 0; i < 3; ++i)
            if (!s_float[i] && !s_oddzero[i]) is64 = 0;
        s_is64 = is64;
    }
    __syncthreads();

    if (!s_float[b]) {
        long long e = ((long long)k * (nnz - 1)) / 63;
        s_vals[b][k] = s_is64 ? p[2 * e] : p[e];
    }
    __syncthreads();
    if (!s_float[b] && k < 63)
        if (s_vals[b][k] > s_vals[b][k + 1]) atomicAnd(&s_sorted[b], 0);
    __syncthreads();

    if (t == 0) {
        int fb = -1, eb = -1, nb = -1;
        for (int i = 0; i < 3; ++i) if (s_float[i]) fb = i;
        for (int i = 0; i < 3; ++i) {
            if (i == fb) continue;
            if (s_sorted[i] && eb < 0) eb = i; else nb = i;
        }
        if (fb < 0) fb = 2;
        if (eb < 0) eb = 1;
        if (nb < 0) nb = 0;
        g_rolemap[0] = nb; g_rolemap[1] = eb; g_rolemap[2] = fb;
        g_is64 = s_is64;
    }
}

// -------------------------------------------------------------- zero cnt ----
__global__ void zero_cnt_kernel() {
    int i = blockIdx.x * blockDim.x + threadIdx.x;
    if (i < N_NODES) g_cnt[i] = 0;
}

// ---- normalize inputs, build edge rowptr, histogram nodes -------------------
__global__ void convert_kernel(const void* b0, const void* b1, const void* b2, int nnz) {
    int i = blockIdx.x * blockDim.x + threadIdx.x;
    if (i >= nnz) return;
    const void* bufs[3] = {b0, b1, b2};
    const void* pn = bufs[g_rolemap[0]];
    const void* pe = bufs[g_rolemap[1]];
    const void* pv = bufs[g_rolemap[2]];
    int is64 = g_is64;
    int n = is64 ? (int)((const long long*)pn)[i] : ((const int*)pn)[i];
    n = min(max(n, 0), N_NODES - 1);
    g_node[i] = n;
    g_val[i]  = ((const float*)pv)[i];
    atomicAdd(&g_cnt[n], 1);

    int ec = is64 ? (int)((const long long*)pe)[i] : ((const int*)pe)[i];
    ec = min(max(ec, 0), N_EDGES - 1);
    g_edge[i] = ec;
    int ep = -1;
    if (i > 0) {
        ep = is64 ? (int)((const long long*)pe)[i - 1] : ((const int*)pe)[i - 1];
        ep = min(max(ep, 0), N_EDGES - 1);
    }
    for (int t = ep + 1; t <= ec; ++t) g_rowptr[t] = i;      // lower_bound fill
    if (i == nnz - 1)
        for (int t = ec + 1; t <= N_EDGES; ++t) g_rowptr[t] = nnz;
}

// ---- exclusive scan of g_cnt -> g_nodeptr, g_pos (single block, 1024 thr) ---
__global__ void scan_kernel(int nnz) {
    __shared__ int s_warp[32];
    const int CH = (N_NODES + 1023) / 1024;   // 98
    int t = threadIdx.x;
    int base = t * CH;
    int local = 0;
    for (int k = 0; k < CH; ++k) {
        int idx = base + k;
        if (idx < N_NODES) local += g_cnt[idx];
    }
    int lane = t & 31, wid = t >> 5;
    int incl = local;
    #pragma unroll
    for (int o = 1; o < 32; o <<= 1) {
        int v = __shfl_up_sync(0xffffffffu, incl, o);
        if (lane >= o) incl += v;
    }
    if (lane == 31) s_warp[wid] = incl;
    __syncthreads();
    if (wid == 0) {
        int v = s_warp[lane];
        #pragma unroll
        for (int o = 1; o < 32; o <<= 1) {
            int u = __shfl_up_sync(0xffffffffu, v, o);
            if (lane >= o) v += u;
        }
        s_warp[lane] = v;
    }
    __syncthreads();
    int run = incl - local + (wid > 0 ? s_warp[wid - 1] : 0);
    for (int k = 0; k < CH; ++k) {
        int idx = base + k;
        if (idx < N_NODES) {
            g_nodeptr[idx] = run;
            g_pos[idx] = run;
            run += g_cnt[idx];
        }
    }
    if (t == 1023) g_nodeptr[N_NODES] = nnz;
}

// ---- scatter nnz into node-sorted order -------------------------------------
__global__ void sort_scatter_kernel(int nnz) {
    int i = blockIdx.x * blockDim.x + threadIdx.x;
    if (i >= nnz) return;
    int n = g_node[i];
    int j = atomicAdd(&g_pos[n], 1);
    g_pe[j] = g_edge[i];
    g_pv[j] = g_val[i];
}

// ---- weight -> W^T pair-packed hi/lo bf16 -----------------------------------
__global__ void wprep_kernel(const float* __restrict__ w) {
    int idx = blockIdx.x * blockDim.x + threadIdx.x;   // 8192 pairs
    if (idx >= C * C / 2) return;
    int n = idx >> 6;
    int k0 = (idx & 63) * 2;
    float a = w[k0 * C + n], b = w[(k0 + 1) * C + n];
    __nv_bfloat16 ah = __float2bfloat16(a), bh = __float2bfloat16(b);
    __nv_bfloat16 al = __float2bfloat16(a - __bfloat162float(ah));
    __nv_bfloat16 bl = __float2bfloat16(b - __bfloat162float(bh));
    g_Wh[idx] = (unsigned)__bfloat16_as_ushort(ah) | ((unsigned)__bfloat16_as_ushort(bh) << 16);
    g_Wl[idx] = (unsigned)__bfloat16_as_ushort(al) | ((unsigned)__bfloat16_as_ushort(bl) << 16);
}

// ------------------------------------------------- node scores: x0 @ a_tgt --
__global__ void node_scores_kernel(const float* __restrict__ x0,
                                   const float* __restrict__ att) {
    int w = (blockIdx.x * blockDim.x + threadIdx.x) >> 5;
    int lane = threadIdx.x & 31;
    if (w >= N_NODES) return;
    float4 a = *reinterpret_cast<const float4*>(att + C + lane * 4);
    float4 x = *reinterpret_cast<const float4*>(x0 + (size_t)w * C + lane * 4);
    float p = x.x * a.x + x.y * a.y + x.z * a.z + x.w * a.w;
    #pragma unroll
    for (int o = 16; o; o >>= 1) p += __shfl_xor_sync(0xffffffffu, p, o);
    if (lane == 0) g_ns[w] = p;
}

// ---- edge pass: m[e] in regs -> store g_M row + g_es (NO atomics) ----------
__global__ void edge_pass_kernel(const float* __restrict__ x0,
                                 const float* __restrict__ att) {
    int w = (blockIdx.x * blockDim.x + threadIdx.x) >> 5;
    int lane = threadIdx.x & 31;
    if (w >= N_EDGES) return;
    int lo = g_rowptr[w];
    int hi = g_rowptr[w + 1];
    if (lo == hi) return;                 // edge never referenced downstream

    float4 acc = make_float4(0.f, 0.f, 0.f, 0.f);
    for (int i = lo; i < hi; ++i) {
        int n = g_node[i];                // warp-uniform -> broadcast
        float v = g_val[i];
        float4 xv = *reinterpret_cast<const float4*>(x0 + (size_t)n * C + lane * 4);
        acc.x = fmaf(v, xv.x, acc.x);
        acc.y = fmaf(v, xv.y, acc.y);
        acc.z = fmaf(v, xv.z, acc.z);
        acc.w = fmaf(v, xv.w, acc.w);
    }

    float4 asrc = *reinterpret_cast<const float4*>(att + lane * 4);
    float es = acc.x * asrc.x + acc.y * asrc.y + acc.z * asrc.z + acc.w * asrc.w;
    #pragma unroll
    for (int o = 16; o; o >>= 1) es += __shfl_xor_sync(0xffffffffu, es, o);

    *reinterpret_cast<float4*>(g_M + (size_t)w * C + lane * 4) = acc;
    if (lane == 0) g_es[w] = es;
}

// ---- node pass: gather m rows by node, accumulate in regs, store T ---------
__global__ void node_pass_kernel() {
    int w = (blockIdx.x * blockDim.x + threadIdx.x) >> 5;
    int lane = threadIdx.x & 31;
    if (w >= N_NODES) return;
    int lo = g_nodeptr[w];
    int hi = g_nodeptr[w + 1];
    float ns = g_ns[w];

    float4 acc = make_float4(0.f, 0.f, 0.f, 0.f);
    for (int j = lo; j < hi; ++j) {
        int e = g_pe[j];                  // warp-uniform broadcast
        float v = g_pv[j];
        float s0 = g_es[e] + ns;
        float sc = (s0 > 0.f ? s0 : expm1f(s0)) * v;
        float4 mv = *reinterpret_cast<const float4*>(g_M + (size_t)e * C + lane * 4);
        acc.x = fmaf(sc, mv.x, acc.x);
        acc.y = fmaf(sc, mv.y, acc.y);
        acc.z = fmaf(sc, mv.z, acc.z);
        acc.w = fmaf(sc, mv.w, acc.w);
    }
    *reinterpret_cast<float4*>(g_T + (size_t)w * C + lane * 4) = acc;
}

// ============== out = T @ W via mma.sync bf16 3-split (base sm_103) ==========
__device__ __forceinline__ void mma_bf16(float* c, const unsigned* a, const unsigned* b) {
    asm volatile(
        "mma.sync.aligned.m16n8k16.row.col.f32.bf16.bf16.f32 "
        "{%0,%1,%2,%3}, {%4,%5,%6,%7}, {%8,%9}, {%0,%1,%2,%3};"
        : "+f"(c[0]), "+f"(c[1]), "+f"(c[2]), "+f"(c[3])
        : "r"(a[0]), "r"(a[1]), "r"(a[2]), "r"(a[3]), "r"(b[0]), "r"(b[1]));
}

#define STR 68   // pair-words per row in smem (64 + 4 pad: conflict-free frags)
// 64-row A tile -> smem 104.5KB -> 2 CTA/SM (16 warps) for latency hiding.
// Warps: wg = wid>>2 selects N half (0:cols 0-63, 1:cols 64-127); wr = wid&3
// selects 16-row group. Each warp: 16 rows x 64 cols (8 n-tiles).
__global__ void __launch_bounds__(256) gemm_mma_kernel(float* __restrict__ out) {
    extern __shared__ unsigned sm[];
    unsigned* Ah = sm;                  // [64][STR]
    unsigned* Al = sm + 64 * STR;
    unsigned* Wh = sm + 2 * 64 * STR;   // [128][STR]
    unsigned* Wl = sm + 2 * 64 * STR + 128 * STR;
    int tid = threadIdx.x, wid = tid >> 5, lane = tid & 31;
    int m0 = blockIdx.x * 64;

    // stage W hi/lo (pair-packed [n][64] in gmem -> padded smem)
    #pragma unroll
    for (int j = 0; j < 32; ++j) {
        int i = tid + j * 256;
        int n = i >> 6, kp = i & 63;
        Wh[n * STR + kp] = g_Wh[i];
        Wl[n * STR + kp] = g_Wl[i];
    }
    // stage A tile: fp32 rows of g_T -> hi/lo bf16 pairs
    for (int i = tid; i < 64 * 64; i += 256) {
        int r = i >> 6, kp = i & 63;
        int grow = m0 + r;
        float a = 0.f, b = 0.f;
        if (grow < N_NODES) {
            float2 v = *reinterpret_cast<const float2*>(g_T + (size_t)grow * C + kp * 2);
            a = v.x; b = v.y;
        }
        __nv_bfloat16 ah = __float2bfloat16(a), bh = __float2bfloat16(b);
        __nv_bfloat16 al = __float2bfloat16(a - __bfloat162float(ah));
        __nv_bfloat16 bl = __float2bfloat16(b - __bfloat162float(bh));
        Ah[r * STR + kp] = (unsigned)__bfloat16_as_ushort(ah) | ((unsigned)__bfloat16_as_ushort(bh) << 16);
        Al[r * STR + kp] = (unsigned)__bfloat16_as_ushort(al) | ((unsigned)__bfloat16_as_ushort(bl) << 16);
    }
    __syncthreads();

    int g = lane >> 2, t = lane & 3;
    int wg = wid >> 2, wr = wid & 3;
    int row = wr * 16 + g;

    float c[8][4];
    #pragma unroll
    for (int nt = 0; nt < 8; ++nt)
        c[nt][0] = c[nt][1] = c[nt][2] = c[nt][3] = 0.f;

    #pragma unroll
    for (int k0 = 0; k0 < 8; ++k0) {   // K chunks of 16 (8 pairs)
        int kb = k0 * 8;
        unsigned ah[4], al[4];
        ah[0] = Ah[row * STR + kb + t];       ah[1] = Ah[(row + 8) * STR + kb + t];
        ah[2] = Ah[row * STR + kb + t + 4];   ah[3] = Ah[(row + 8) * STR + kb + t + 4];
        al[0] = Al[row * STR + kb + t];       al[1] = Al[(row + 8) * STR + kb + t];
        al[2] = Al[row * STR + kb + t + 4];   al[3] = Al[(row + 8) * STR + kb + t + 4];
        #pragma unroll
        for (int nt = 0; nt < 8; ++nt) {
            int n = wg * 64 + nt * 8 + g;
            unsigned bh[2], bl[2];
            bh[0] = Wh[n * STR + kb + t]; bh[1] = Wh[n * STR + kb + t + 4];
            bl[0] = Wl[n * STR + kb + t]; bl[1] = Wl[n * STR + kb + t + 4];
            mma_bf16(c[nt], ah, bh);   // Th*Wh
            mma_bf16(c[nt], ah, bl);   // Th*Wl
            mma_bf16(c[nt], al, bh);   // Tl*Wh
        }
    }

    int grow0 = m0 + row, grow1 = grow0 + 8;
    #pragma unroll
    for (int nt = 0; nt < 8; ++nt) {
        int col = wg * 64 + nt * 8 + 2 * t;
        if (grow0 < N_NODES)
            *reinterpret_cast<float2*>(out + (size_t)grow0 * C + col) = make_float2(c[nt][0], c[nt][1]);
        if (grow1 < N_NODES)
            *reinterpret_cast<float2*>(out + (size_t)grow1 * C + col) = make_float2(c[nt][2], c[nt][3]);
    }
}
#define GEMM_SMEM ((2 * 64 + 2 * 128) * STR * 4)   // 104448 B

// -----------------------------------------------------------------------------
extern "C" void kernel_launch(void* const* d_in, const int* in_sizes, int n_in,
                              void* d_out, int out_size) {
    const float* x0 = nullptr; const float* weight = nullptr; const float* att = nullptr;
    const void* big[3] = {nullptr, nullptr, nullptr};
    int nnz = 0, big_seen = 0;
    for (int i = 0; i < n_in; ++i) {
        int sz = in_sizes[i];
        if (sz == N_NODES * C)      x0 = (const float*)d_in[i];
        else if (sz == C * C)       weight = (const float*)d_in[i];
        else if (sz == 2 * C)       att = (const float*)d_in[i];
        else if (big_seen < 3)      { big[big_seen++] = d_in[i]; nnz = sz; }
    }
    float* out = (float*)d_out;

    detect_kernel<<<1, 192>>>((const unsigned*)big[0], (const unsigned*)big[1],
                              (const unsigned*)big[2], nnz);
    zero_cnt_kernel<<<(N_NODES + 255) / 256, 256>>>();
    convert_kernel<<<(nnz + 255) / 256, 256>>>(big[0], big[1], big[2], nnz);
    scan_kernel<<<1, 1024>>>(nnz);
    sort_scatter_kernel<<<(nnz + 255) / 256, 256>>>(nnz);
    wprep_kernel<<<(C * C / 2 + 255) / 256, 256>>>(weight);
    node_scores_kernel<<<(N_NODES * 32 + 255) / 256, 256>>>(x0, att);
    edge_pass_kernel<<<(N_EDGES * 32 + 255) / 256, 256>>>(x0, att);
    node_pass_kernel<<<(N_NODES * 32 + 255) / 256, 256>>>();

    cudaFuncSetAttribute(gemm_mma_kernel,
                         cudaFuncAttributeMaxDynamicSharedMemorySize, GEMM_SMEM);
    gemm_mma_kernel<<<(N_NODES + 63) / 64, 256, GEMM_SMEM>>>(out);
}

// round 7
// speedup vs baseline: 1.6125x; 1.6125x over previous
#include <cuda_runtime.h>
#include <cuda_bf16.h>
#include <math.h>
#include <stdint.h>

#define N_NODES 100000
#define N_EDGES 100000
#define NNZ_MAX 1600000
#define C 128

// ---- scratch (device globals; allocation-free per harness rules) -----------
__device__ __align__(16) float g_T[(size_t)N_NODES * C];  // scatter target (51.2MB)
__device__ float g_ns[N_NODES];                           // x0 @ a_tgt
__device__ float g_es[N_EDGES];
__device__ int   g_rowptr[N_EDGES + 1];
__device__ int   g_node[NNZ_MAX];
__device__ float g_val[NNZ_MAX];
__device__ int   g_is64;
__device__ int   g_rolemap[3];
// W^T pair-packed bf16 hi/lo: g_Wh[n*64 + kp] = {W[2kp][n], W[2kp+1][n]}
__device__ __align__(16) unsigned g_Wh[C * C / 2];
__device__ __align__(16) unsigned g_Wl[C * C / 2];

// ---- detect dtype (int32 vs int64) and buffer roles on-device --------------
__global__ void detect_kernel(const unsigned* __restrict__ b0,
                              const unsigned* __restrict__ b1,
                              const unsigned* __restrict__ b2, int nnz) {
    __shared__ int s_float[3], s_oddzero[3], s_sorted[3], s_is64;
    __shared__ unsigned s_vals[3][64];
    int t = threadIdx.x;
    int b = t >> 6, k = t & 63;
    const unsigned* bufs[3] = {b0, b1, b2};
    if (t < 3) { s_float[t] = 1; s_oddzero[t] = 1; s_sorted[t] = 1; }
    __syncthreads();

    const unsigned* p = bufs[b];
    unsigned q = (unsigned)(((long long)k * (nnz - 2)) / 63);
    unsigned w_even = p[q & ~1u];
    unsigned w_odd  = p[q | 1u];
    if (w_even <= 0x01000000u) atomicAnd(&s_float[b], 0);
    if (w_odd != 0u)           atomicAnd(&s_oddzero[b], 0);
    __syncthreads();

    if (t == 0) {
        int is64 = 1;
        for (int i = 0; i < 3; ++i)
            if (!s_float[i] && !s_oddzero[i]) is64 = 0;
        s_is64 = is64;
    }
    __syncthreads();

    if (!s_float[b]) {
        long long e = ((long long)k * (nnz - 1)) / 63;
        s_vals[b][k] = s_is64 ? p[2 * e] : p[e];
    }
    __syncthreads();
    if (!s_float[b] && k < 63)
        if (s_vals[b][k] > s_vals[b][k + 1]) atomicAnd(&s_sorted[b], 0);
    __syncthreads();

    if (t == 0) {
        int fb = -1, eb = -1, nb = -1;
        for (int i = 0; i < 3; ++i) if (s_float[i]) fb = i;
        for (int i = 0; i < 3; ++i) {
            if (i == fb) continue;
            if (s_sorted[i] && eb < 0) eb = i; else nb = i;
        }
        if (fb < 0) fb = 2;
        if (eb < 0) eb = 1;
        if (nb < 0) nb = 0;
        g_rolemap[0] = nb; g_rolemap[1] = eb; g_rolemap[2] = fb;
        g_is64 = s_is64;
    }
}

// ---- normalize inputs, build rowptr by boundary-fill, zero g_T --------------
__global__ void convert_kernel(const void* b0, const void* b1, const void* b2, int nnz) {
    int i = blockIdx.x * blockDim.x + threadIdx.x;
    // grid-stride zeroing of g_T (coalesced float4)
    {
        int nt = gridDim.x * blockDim.x;
        float4* T4 = reinterpret_cast<float4*>(g_T);
        const int total4 = N_NODES * C / 4;    // 3.2M
        for (int idx = i; idx < total4; idx += nt)
            T4[idx] = make_float4(0.f, 0.f, 0.f, 0.f);
    }
    if (i >= nnz) return;
    const void* bufs[3] = {b0, b1, b2};
    const void* pn = bufs[g_rolemap[0]];
    const void* pe = bufs[g_rolemap[1]];
    const void* pv = bufs[g_rolemap[2]];
    int is64 = g_is64;
    int n = is64 ? (int)((const long long*)pn)[i] : ((const int*)pn)[i];
    g_node[i] = min(max(n, 0), N_NODES - 1);
    g_val[i]  = ((const float*)pv)[i];

    int ec = is64 ? (int)((const long long*)pe)[i] : ((const int*)pe)[i];
    ec = min(max(ec, 0), N_EDGES - 1);
    int ep = -1;
    if (i > 0) {
        ep = is64 ? (int)((const long long*)pe)[i - 1] : ((const int*)pe)[i - 1];
        ep = min(max(ep, 0), N_EDGES - 1);
    }
    for (int t = ep + 1; t <= ec; ++t) g_rowptr[t] = i;      // lower_bound fill
    if (i == nnz - 1)
        for (int t = ec + 1; t <= N_EDGES; ++t) g_rowptr[t] = nnz;
}

// ---- weight -> W^T pair-packed hi/lo bf16 -----------------------------------
__global__ void wprep_kernel(const float* __restrict__ w) {
    int idx = blockIdx.x * blockDim.x + threadIdx.x;   // 8192 pairs
    if (idx >= C * C / 2) return;
    int n = idx >> 6;
    int k0 = (idx & 63) * 2;
    float a = w[k0 * C + n], b = w[(k0 + 1) * C + n];
    __nv_bfloat16 ah = __float2bfloat16(a), bh = __float2bfloat16(b);
    __nv_bfloat16 al = __float2bfloat16(a - __bfloat162float(ah));
    __nv_bfloat16 bl = __float2bfloat16(b - __bfloat162float(bh));
    g_Wh[idx] = (unsigned)__bfloat16_as_ushort(ah) | ((unsigned)__bfloat16_as_ushort(bh) << 16);
    g_Wl[idx] = (unsigned)__bfloat16_as_ushort(al) | ((unsigned)__bfloat16_as_ushort(bl) << 16);
}

// ------------------------------------------------- node scores: x0 @ a_tgt --
__global__ void node_scores_kernel(const float* __restrict__ x0,
                                   const float* __restrict__ att) {
    int w = (blockIdx.x * blockDim.x + threadIdx.x) >> 5;
    int lane = threadIdx.x & 31;
    if (w >= N_NODES) return;
    float4 a = *reinterpret_cast<const float4*>(att + C + lane * 4);
    float4 x = *reinterpret_cast<const float4*>(x0 + (size_t)w * C + lane * 4);
    float p = x.x * a.x + x.y * a.y + x.z * a.z + x.w * a.w;
    #pragma unroll
    for (int o = 16; o; o >>= 1) p += __shfl_xor_sync(0xffffffffu, p, o);
    if (lane == 0) g_ns[w] = p;
}

// ---- fused per-edge: segment sum (m in regs) + score + red.v4 scatter -------
// Software-pipelined (2-deep) in BOTH loops to raise MLP toward LTS saturation.
__global__ void edge_fused_kernel(const float* __restrict__ x0,
                                  const float* __restrict__ att) {
    int w = (blockIdx.x * blockDim.x + threadIdx.x) >> 5;
    int lane = threadIdx.x & 31;
    if (w >= N_EDGES) return;
    int lo = g_rowptr[w];
    int hi = g_rowptr[w + 1];
    if (lo == hi) return;

    // ---- gather loop: acc = sum v_i * x0[n_i], pipelined ----
    float4 acc = make_float4(0.f, 0.f, 0.f, 0.f);
    int   n0 = g_node[lo];
    float v0 = g_val[lo];
    float4 xv0 = *reinterpret_cast<const float4*>(x0 + (size_t)n0 * C + lane * 4);
    for (int i = lo + 1; i < hi; ++i) {
        int   n1 = g_node[i];
        float v1 = g_val[i];
        float4 xv1 = *reinterpret_cast<const float4*>(x0 + (size_t)n1 * C + lane * 4);
        acc.x = fmaf(v0, xv0.x, acc.x);
        acc.y = fmaf(v0, xv0.y, acc.y);
        acc.z = fmaf(v0, xv0.z, acc.z);
        acc.w = fmaf(v0, xv0.w, acc.w);
        v0 = v1; xv0 = xv1;
    }
    acc.x = fmaf(v0, xv0.x, acc.x);
    acc.y = fmaf(v0, xv0.y, acc.y);
    acc.z = fmaf(v0, xv0.z, acc.z);
    acc.w = fmaf(v0, xv0.w, acc.w);

    float4 asrc = *reinterpret_cast<const float4*>(att + lane * 4);
    float es = acc.x * asrc.x + acc.y * asrc.y + acc.z * asrc.z + acc.w * asrc.w;
    #pragma unroll
    for (int o = 16; o; o >>= 1) es += __shfl_xor_sync(0xffffffffu, es, o);

    // ---- scatter loop: red.v4 T[n_i] += elu(es+ns[n_i])*v_i * acc, pipelined ----
    int   sn0 = g_node[lo];
    float sv0 = g_val[lo];
    float ns0 = g_ns[sn0];
    for (int i = lo + 1; i < hi; ++i) {
        int   sn1 = g_node[i];
        float sv1 = g_val[i];
        float ns1 = g_ns[sn1];
        float s = es + ns0;
        float sc = (s > 0.f ? s : expm1f(s)) * sv0;
        float* dst = g_T + (size_t)sn0 * C + lane * 4;
        asm volatile("red.global.add.v4.f32 [%0], {%1,%2,%3,%4};"
                     :: "l"(dst), "f"(sc * acc.x), "f"(sc * acc.y),
                        "f"(sc * acc.z), "f"(sc * acc.w)
                     : "memory");
        sn0 = sn1; sv0 = sv1; ns0 = ns1;
    }
    {
        float s = es + ns0;
        float sc = (s > 0.f ? s : expm1f(s)) * sv0;
        float* dst = g_T + (size_t)sn0 * C + lane * 4;
        asm volatile("red.global.add.v4.f32 [%0], {%1,%2,%3,%4};"
                     :: "l"(dst), "f"(sc * acc.x), "f"(sc * acc.y),
                        "f"(sc * acc.z), "f"(sc * acc.w)
                     : "memory");
    }
}

// ============== out = T @ W via mma.sync bf16 3-split (base sm_103) ==========
__device__ __forceinline__ void mma_bf16(float* c, const unsigned* a, const unsigned* b) {
    asm volatile(
        "mma.sync.aligned.m16n8k16.row.col.f32.bf16.bf16.f32 "
        "{%0,%1,%2,%3}, {%4,%5,%6,%7}, {%8,%9}, {%0,%1,%2,%3};"
        : "+f"(c[0]), "+f"(c[1]), "+f"(c[2]), "+f"(c[3])
        : "r"(a[0]), "r"(a[1]), "r"(a[2]), "r"(a[3]), "r"(b[0]), "r"(b[1]));
}

#define STR 68   // pair-words per row in smem (64 + 4 pad: conflict-free frags)

__global__ void __launch_bounds__(256, 1) gemm_mma_kernel(float* __restrict__ out) {
    extern __shared__ unsigned sm[];
    unsigned* Ah = sm;                 // [128][STR]
    unsigned* Al = sm + 128 * STR;
    unsigned* Wh = sm + 2 * 128 * STR;
    unsigned* Wl = sm + 3 * 128 * STR;
    int tid = threadIdx.x, wid = tid >> 5, lane = tid & 31;
    int m0 = blockIdx.x * 128;

    #pragma unroll
    for (int j = 0; j < 32; ++j) {
        int i = tid + j * 256;
        int n = i >> 6, kp = i & 63;
        Wh[n * STR + kp] = g_Wh[i];
        Wl[n * STR + kp] = g_Wl[i];
    }
    for (int i = tid; i < C * C / 2; i += 256) {
        int r = i >> 6, kp = i & 63;
        int grow = m0 + r;
        float a = 0.f, b = 0.f;
        if (grow < N_NODES) {
            float2 v = *reinterpret_cast<const float2*>(g_T + (size_t)grow * C + kp * 2);
            a = v.x; b = v.y;
        }
        __nv_bfloat16 ah = __float2bfloat16(a), bh = __float2bfloat16(b);
        __nv_bfloat16 al = __float2bfloat16(a - __bfloat162float(ah));
        __nv_bfloat16 bl = __float2bfloat16(b - __bfloat162float(bh));
        Ah[r * STR + kp] = (unsigned)__bfloat16_as_ushort(ah) | ((unsigned)__bfloat16_as_ushort(bh) << 16);
        Al[r * STR + kp] = (unsigned)__bfloat16_as_ushort(al) | ((unsigned)__bfloat16_as_ushort(bl) << 16);
    }
    __syncthreads();

    int g = lane >> 2, t = lane & 3;
    int row = wid * 16 + g;

    float c[16][4];
    #pragma unroll
    for (int nt = 0; nt < 16; ++nt)
        c[nt][0] = c[nt][1] = c[nt][2] = c[nt][3] = 0.f;

    #pragma unroll
    for (int k0 = 0; k0 < 8; ++k0) {
        int kb = k0 * 8;
        unsigned ah[4], al[4];
        ah[0] = Ah[row * STR + kb + t];       ah[1] = Ah[(row + 8) * STR + kb + t];
        ah[2] = Ah[row * STR + kb + t + 4];   ah[3] = Ah[(row + 8) * STR + kb + t + 4];
        al[0] = Al[row * STR + kb + t];       al[1] = Al[(row + 8) * STR + kb + t];
        al[2] = Al[row * STR + kb + t + 4];   al[3] = Al[(row + 8) * STR + kb + t + 4];
        #pragma unroll
        for (int nt = 0; nt < 16; ++nt) {
            int n = nt * 8 + g;
            unsigned bh[2], bl[2];
            bh[0] = Wh[n * STR + kb + t]; bh[1] = Wh[n * STR + kb + t + 4];
            bl[0] = Wl[n * STR + kb + t]; bl[1] = Wl[n * STR + kb + t + 4];
            mma_bf16(c[nt], ah, bh);
            mma_bf16(c[nt], ah, bl);
            mma_bf16(c[nt], al, bh);
        }
    }

    int grow0 = m0 + row, grow1 = grow0 + 8;
    #pragma unroll
    for (int nt = 0; nt < 16; ++nt) {
        int col = nt * 8 + 2 * t;
        if (grow0 < N_NODES)
            *reinterpret_cast<float2*>(out + (size_t)grow0 * C + col) = make_float2(c[nt][0], c[nt][1]);
        if (grow1 < N_NODES)
            *reinterpret_cast<float2*>(out + (size_t)grow1 * C + col) = make_float2(c[nt][2], c[nt][3]);
    }
}
#define GEMM_SMEM (4 * 128 * STR * 4)   // 139264 B

// -----------------------------------------------------------------------------
extern "C" void kernel_launch(void* const* d_in, const int* in_sizes, int n_in,
                              void* d_out, int out_size) {
    const float* x0 = nullptr; const float* weight = nullptr; const float* att = nullptr;
    const void* big[3] = {nullptr, nullptr, nullptr};
    int nnz = 0, big_seen = 0;
    for (int i = 0; i < n_in; ++i) {
        int sz = in_sizes[i];
        if (sz == N_NODES * C)      x0 = (const float*)d_in[i];
        else if (sz == C * C)       weight = (const float*)d_in[i];
        else if (sz == 2 * C)       att = (const float*)d_in[i];
        else if (big_seen < 3)      { big[big_seen++] = d_in[i]; nnz = sz; }
    }
    float* out = (float*)d_out;

    // Launch order chosen so edge_fused is launch #4 (the ncu-profiled slot).
    detect_kernel<<<1, 192>>>((const unsigned*)big[0], (const unsigned*)big[1],
                              (const unsigned*)big[2], nnz);
    convert_kernel<<<(nnz + 255) / 256, 256>>>(big[0], big[1], big[2], nnz);  // also zeroes g_T
    node_scores_kernel<<<(N_NODES * 32 + 255) / 256, 256>>>(x0, att);
    edge_fused_kernel<<<(N_EDGES * 32 + 255) / 256, 256>>>(x0, att);          // slot 4
    wprep_kernel<<<(C * C / 2 + 255) / 256, 256>>>(weight);

    cudaFuncSetAttribute(gemm_mma_kernel,
                         cudaFuncAttributeMaxDynamicSharedMemorySize, GEMM_SMEM);
    gemm_mma_kernel<<<(N_NODES + 127) / 128, 256, GEMM_SMEM>>>(out);
}

// round 8
// speedup vs baseline: 1.7939x; 1.1125x over previous
#include <cuda_runtime.h>
#include <cuda_bf16.h>
#include <cuda_fp16.h>
#include <math.h>
#include <stdint.h>

#define N_NODES 100000
#define N_EDGES 100000
#define NNZ_MAX 1600000
#define C 128

// ---- scratch (device globals; allocation-free per harness rules) -----------
__device__ __align__(16) float  g_T[(size_t)N_NODES * C];   // scatter target (51.2MB)
__device__ __align__(16) __half g_x0h[(size_t)N_NODES * C]; // fp16 copy of x0 (25.6MB)
__device__ float g_ns[N_NODES];                             // x0 @ a_tgt
__device__ int   g_rowptr[N_EDGES + 1];
__device__ int   g_node[NNZ_MAX];
__device__ float g_val[NNZ_MAX];
__device__ int   g_is64;
__device__ int   g_rolemap[3];
// W^T pair-packed bf16 hi/lo: g_Wh[n*64 + kp] = {W[2kp][n], W[2kp+1][n]}
__device__ __align__(16) unsigned g_Wh[C * C / 2];
__device__ __align__(16) unsigned g_Wl[C * C / 2];

// ---- detect dtype (int32 vs int64) and buffer roles on-device --------------
__global__ void detect_kernel(const unsigned* __restrict__ b0,
                              const unsigned* __restrict__ b1,
                              const unsigned* __restrict__ b2, int nnz) {
    __shared__ int s_float[3], s_oddzero[3], s_sorted[3], s_is64;
    __shared__ unsigned s_vals[3][64];
    int t = threadIdx.x;
    int b = t >> 6, k = t & 63;
    const unsigned* bufs[3] = {b0, b1, b2};
    if (t < 3) { s_float[t] = 1; s_oddzero[t] = 1; s_sorted[t] = 1; }
    __syncthreads();

    const unsigned* p = bufs[b];
    unsigned q = (unsigned)(((long long)k * (nnz - 2)) / 63);
    unsigned w_even = p[q & ~1u];
    unsigned w_odd  = p[q | 1u];
    if (w_even <= 0x01000000u) atomicAnd(&s_float[b], 0);
    if (w_odd != 0u)           atomicAnd(&s_oddzero[b], 0);
    __syncthreads();

    if (t == 0) {
        int is64 = 1;
        for (int i = 0; i < 3; ++i)
            if (!s_float[i] && !s_oddzero[i]) is64 = 0;
        s_is64 = is64;
    }
    __syncthreads();

    if (!s_float[b]) {
        long long e = ((long long)k * (nnz - 1)) / 63;
        s_vals[b][k] = s_is64 ? p[2 * e] : p[e];
    }
    __syncthreads();
    if (!s_float[b] && k < 63)
        if (s_vals[b][k] > s_vals[b][k + 1]) atomicAnd(&s_sorted[b], 0);
    __syncthreads();

    if (t == 0) {
        int fb = -1, eb = -1, nb = -1;
        for (int i = 0; i < 3; ++i) if (s_float[i]) fb = i;
        for (int i = 0; i < 3; ++i) {
            if (i == fb) continue;
            if (s_sorted[i] && eb < 0) eb = i; else nb = i;
        }
        if (fb < 0) fb = 2;
        if (eb < 0) eb = 1;
        if (nb < 0) nb = 0;
        g_rolemap[0] = nb; g_rolemap[1] = eb; g_rolemap[2] = fb;
        g_is64 = s_is64;
    }
}

// ---- normalize inputs, build rowptr by boundary-fill, zero g_T --------------
__global__ void convert_kernel(const void* b0, const void* b1, const void* b2, int nnz) {
    int i = blockIdx.x * blockDim.x + threadIdx.x;
    {   // grid-stride zeroing of g_T (coalesced float4)
        int nt = gridDim.x * blockDim.x;
        float4* T4 = reinterpret_cast<float4*>(g_T);
        const int total4 = N_NODES * C / 4;
        for (int idx = i; idx < total4; idx += nt)
            T4[idx] = make_float4(0.f, 0.f, 0.f, 0.f);
    }
    if (i >= nnz) return;
    const void* bufs[3] = {b0, b1, b2};
    const void* pn = bufs[g_rolemap[0]];
    const void* pe = bufs[g_rolemap[1]];
    const void* pv = bufs[g_rolemap[2]];
    int is64 = g_is64;
    int n = is64 ? (int)((const long long*)pn)[i] : ((const int*)pn)[i];
    g_node[i] = min(max(n, 0), N_NODES - 1);
    g_val[i]  = ((const float*)pv)[i];

    int ec = is64 ? (int)((const long long*)pe)[i] : ((const int*)pe)[i];
    ec = min(max(ec, 0), N_EDGES - 1);
    int ep = -1;
    if (i > 0) {
        ep = is64 ? (int)((const long long*)pe)[i - 1] : ((const int*)pe)[i - 1];
        ep = min(max(ep, 0), N_EDGES - 1);
    }
    for (int t = ep + 1; t <= ec; ++t) g_rowptr[t] = i;      // lower_bound fill
    if (i == nnz - 1)
        for (int t = ec + 1; t <= N_EDGES; ++t) g_rowptr[t] = nnz;
}

// ---- weight -> W^T pair-packed hi/lo bf16 -----------------------------------
__global__ void wprep_kernel(const float* __restrict__ w) {
    int idx = blockIdx.x * blockDim.x + threadIdx.x;   // 8192 pairs
    if (idx >= C * C / 2) return;
    int n = idx >> 6;
    int k0 = (idx & 63) * 2;
    float a = w[k0 * C + n], b = w[(k0 + 1) * C + n];
    __nv_bfloat16 ah = __float2bfloat16(a), bh = __float2bfloat16(b);
    __nv_bfloat16 al = __float2bfloat16(a - __bfloat162float(ah));
    __nv_bfloat16 bl = __float2bfloat16(b - __bfloat162float(bh));
    g_Wh[idx] = (unsigned)__bfloat16_as_ushort(ah) | ((unsigned)__bfloat16_as_ushort(bh) << 16);
    g_Wl[idx] = (unsigned)__bfloat16_as_ushort(al) | ((unsigned)__bfloat16_as_ushort(bl) << 16);
}

// ---- node scores: x0 @ a_tgt; ALSO emits fp16 copy of x0 (free: x0 already streamed)
__global__ void node_scores_kernel(const float* __restrict__ x0,
                                   const float* __restrict__ att) {
    int w = (blockIdx.x * blockDim.x + threadIdx.x) >> 5;
    int lane = threadIdx.x & 31;
    if (w >= N_NODES) return;
    float4 a = *reinterpret_cast<const float4*>(att + C + lane * 4);
    float4 x = *reinterpret_cast<const float4*>(x0 + (size_t)w * C + lane * 4);

    // fp16 copy (4 channels per lane, 8B coalesced store)
    __half2 h01 = __floats2half2_rn(x.x, x.y);
    __half2 h23 = __floats2half2_rn(x.z, x.w);
    uint2 hv;
    hv.x = *reinterpret_cast<unsigned*>(&h01);
    hv.y = *reinterpret_cast<unsigned*>(&h23);
    *reinterpret_cast<uint2*>(g_x0h + (size_t)w * C + lane * 4) = hv;

    float p = x.x * a.x + x.y * a.y + x.z * a.z + x.w * a.w;
    #pragma unroll
    for (int o = 16; o; o >>= 1) p += __shfl_xor_sync(0xffffffffu, p, o);
    if (lane == 0) g_ns[w] = p;
}

// ---- fused per-edge: segment sum (fp16 gather, fp32 acc) + score + red.v4 ---
__global__ void edge_fused_kernel(const float* __restrict__ att) {
    int w = (blockIdx.x * blockDim.x + threadIdx.x) >> 5;
    int lane = threadIdx.x & 31;
    if (w >= N_EDGES) return;
    int lo = g_rowptr[w];
    int hi = g_rowptr[w + 1];
    if (lo == hi) return;

    // ---- gather loop (fp16 rows, 256B/warp), 2-deep pipelined ----
    float4 acc = make_float4(0.f, 0.f, 0.f, 0.f);
    int   n0 = g_node[lo];
    float v0 = g_val[lo];
    uint2 hv0 = *reinterpret_cast<const uint2*>(g_x0h + (size_t)n0 * C + lane * 4);
    for (int i = lo + 1; i < hi; ++i) {
        int   n1 = g_node[i];
        float v1 = g_val[i];
        uint2 hv1 = *reinterpret_cast<const uint2*>(g_x0h + (size_t)n1 * C + lane * 4);
        float2 f01 = __half22float2(*reinterpret_cast<__half2*>(&hv0.x));
        float2 f23 = __half22float2(*reinterpret_cast<__half2*>(&hv0.y));
        acc.x = fmaf(v0, f01.x, acc.x);
        acc.y = fmaf(v0, f01.y, acc.y);
        acc.z = fmaf(v0, f23.x, acc.z);
        acc.w = fmaf(v0, f23.y, acc.w);
        v0 = v1; hv0 = hv1;
    }
    {
        float2 f01 = __half22float2(*reinterpret_cast<__half2*>(&hv0.x));
        float2 f23 = __half22float2(*reinterpret_cast<__half2*>(&hv0.y));
        acc.x = fmaf(v0, f01.x, acc.x);
        acc.y = fmaf(v0, f01.y, acc.y);
        acc.z = fmaf(v0, f23.x, acc.z);
        acc.w = fmaf(v0, f23.y, acc.w);
    }

    float4 asrc = *reinterpret_cast<const float4*>(att + lane * 4);
    float es = acc.x * asrc.x + acc.y * asrc.y + acc.z * asrc.z + acc.w * asrc.w;
    #pragma unroll
    for (int o = 16; o; o >>= 1) es += __shfl_xor_sync(0xffffffffu, es, o);

    // ---- scatter loop: red.v4 T[n_i] += elu(es+ns[n_i])*v_i * acc, pipelined ----
    int   sn0 = g_node[lo];
    float sv0 = g_val[lo];
    float ns0 = g_ns[sn0];
    for (int i = lo + 1; i < hi; ++i) {
        int   sn1 = g_node[i];
        float sv1 = g_val[i];
        float ns1 = g_ns[sn1];
        float s = es + ns0;
        float sc = (s > 0.f ? s : expm1f(s)) * sv0;
        float* dst = g_T + (size_t)sn0 * C + lane * 4;
        asm volatile("red.global.add.v4.f32 [%0], {%1,%2,%3,%4};"
                     :: "l"(dst), "f"(sc * acc.x), "f"(sc * acc.y),
                        "f"(sc * acc.z), "f"(sc * acc.w)
                     : "memory");
        sn0 = sn1; sv0 = sv1; ns0 = ns1;
    }
    {
        float s = es + ns0;
        float sc = (s > 0.f ? s : expm1f(s)) * sv0;
        float* dst = g_T + (size_t)sn0 * C + lane * 4;
        asm volatile("red.global.add.v4.f32 [%0], {%1,%2,%3,%4};"
                     :: "l"(dst), "f"(sc * acc.x), "f"(sc * acc.y),
                        "f"(sc * acc.z), "f"(sc * acc.w)
                     : "memory");
    }
}

// ============== out = T @ W via mma.sync bf16 3-split (base sm_103) ==========
__device__ __forceinline__ void mma_bf16(float* c, const unsigned* a, const unsigned* b) {
    asm volatile(
        "mma.sync.aligned.m16n8k16.row.col.f32.bf16.bf16.f32 "
        "{%0,%1,%2,%3}, {%4,%5,%6,%7}, {%8,%9}, {%0,%1,%2,%3};"
        : "+f"(c[0]), "+f"(c[1]), "+f"(c[2]), "+f"(c[3])
        : "r"(a[0]), "r"(a[1]), "r"(a[2]), "r"(a[3]), "r"(b[0]), "r"(b[1]));
}

#define STR 68   // pair-words per row in smem (64 + 4 pad: conflict-free frags)

__global__ void __launch_bounds__(256, 1) gemm_mma_kernel(float* __restrict__ out) {
    extern __shared__ unsigned sm[];
    unsigned* Ah = sm;                 // [128][STR]
    unsigned* Al = sm + 128 * STR;
    unsigned* Wh = sm + 2 * 128 * STR;
    unsigned* Wl = sm + 3 * 128 * STR;
    int tid = threadIdx.x, wid = tid >> 5, lane = tid & 31;
    int m0 = blockIdx.x * 128;

    #pragma unroll
    for (int j = 0; j < 32; ++j) {
        int i = tid + j * 256;
        int n = i >> 6, kp = i & 63;
        Wh[n * STR + kp] = g_Wh[i];
        Wl[n * STR + kp] = g_Wl[i];
    }
    for (int i = tid; i < C * C / 2; i += 256) {
        int r = i >> 6, kp = i & 63;
        int grow = m0 + r;
        float a = 0.f, b = 0.f;
        if (grow < N_NODES) {
            float2 v = *reinterpret_cast<const float2*>(g_T + (size_t)grow * C + kp * 2);
            a = v.x; b = v.y;
        }
        __nv_bfloat16 ah = __float2bfloat16(a), bh = __float2bfloat16(b);
        __nv_bfloat16 al = __float2bfloat16(a - __bfloat162float(ah));
        __nv_bfloat16 bl = __float2bfloat16(b - __bfloat162float(bh));
        Ah[r * STR + kp] = (unsigned)__bfloat16_as_ushort(ah) | ((unsigned)__bfloat16_as_ushort(bh) << 16);
        Al[r * STR + kp] = (unsigned)__bfloat16_as_ushort(al) | ((unsigned)__bfloat16_as_ushort(bl) << 16);
    }
    __syncthreads();

    int g = lane >> 2, t = lane & 3;
    int row = wid * 16 + g;

    float c[16][4];
    #pragma unroll
    for (int nt = 0; nt < 16; ++nt)
        c[nt][0] = c[nt][1] = c[nt][2] = c[nt][3] = 0.f;

    #pragma unroll
    for (int k0 = 0; k0 < 8; ++k0) {
        int kb = k0 * 8;
        unsigned ah[4], al[4];
        ah[0] = Ah[row * STR + kb + t];       ah[1] = Ah[(row + 8) * STR + kb + t];
        ah[2] = Ah[row * STR + kb + t + 4];   ah[3] = Ah[(row + 8) * STR + kb + t + 4];
        al[0] = Al[row * STR + kb + t];       al[1] = Al[(row + 8) * STR + kb + t];
        al[2] = Al[row * STR + kb + t + 4];   al[3] = Al[(row + 8) * STR + kb + t + 4];
        #pragma unroll
        for (int nt = 0; nt < 16; ++nt) {
            int n = nt * 8 + g;
            unsigned bh[2], bl[2];
            bh[0] = Wh[n * STR + kb + t]; bh[1] = Wh[n * STR + kb + t + 4];
            bl[0] = Wl[n * STR + kb + t]; bl[1] = Wl[n * STR + kb + t + 4];
            mma_bf16(c[nt], ah, bh);
            mma_bf16(c[nt], ah, bl);
            mma_bf16(c[nt], al, bh);
        }
    }

    int grow0 = m0 + row, grow1 = grow0 + 8;
    #pragma unroll
    for (int nt = 0; nt < 16; ++nt) {
        int col = nt * 8 + 2 * t;
        if (grow0 < N_NODES)
            *reinterpret_cast<float2*>(out + (size_t)grow0 * C + col) = make_float2(c[nt][0], c[nt][1]);
        if (grow1 < N_NODES)
            *reinterpret_cast<float2*>(out + (size_t)grow1 * C + col) = make_float2(c[nt][2], c[nt][3]);
    }
}
#define GEMM_SMEM (4 * 128 * STR * 4)   // 139264 B

// -----------------------------------------------------------------------------
extern "C" void kernel_launch(void* const* d_in, const int* in_sizes, int n_in,
                              void* d_out, int out_size) {
    const float* x0 = nullptr; const float* weight = nullptr; const float* att = nullptr;
    const void* big[3] = {nullptr, nullptr, nullptr};
    int nnz = 0, big_seen = 0;
    for (int i = 0; i < n_in; ++i) {
        int sz = in_sizes[i];
        if (sz == N_NODES * C)      x0 = (const float*)d_in[i];
        else if (sz == C * C)       weight = (const float*)d_in[i];
        else if (sz == 2 * C)       att = (const float*)d_in[i];
        else if (big_seen < 3)      { big[big_seen++] = d_in[i]; nnz = sz; }
    }
    float* out = (float*)d_out;

    // edge_fused kept at launch slot #4 (the ncu-profiled slot).
    detect_kernel<<<1, 192>>>((const unsigned*)big[0], (const unsigned*)big[1],
                              (const unsigned*)big[2], nnz);
    convert_kernel<<<(nnz + 255) / 256, 256>>>(big[0], big[1], big[2], nnz);  // also zeroes g_T
    node_scores_kernel<<<(N_NODES * 32 + 255) / 256, 256>>>(x0, att);         // also emits g_x0h
    edge_fused_kernel<<<(N_EDGES * 32 + 255) / 256, 256>>>(att);              // slot 4
    wprep_kernel<<<(C * C / 2 + 255) / 256, 256>>>(weight);

    cudaFuncSetAttribute(gemm_mma_kernel,
                         cudaFuncAttributeMaxDynamicSharedMemorySize, GEMM_SMEM);
    gemm_mma_kernel<<<(N_NODES + 127) / 128, 256, GEMM_SMEM>>>(out);
}

// round 9
// speedup vs baseline: 1.8262x; 1.0180x over previous
#include <cuda_runtime.h>
#include <cuda_bf16.h>
#include <cuda_fp16.h>
#include <math.h>
#include <stdint.h>

#define N_NODES 100000
#define N_EDGES 100000
#define NNZ_MAX 1600000
#define C 128

// ---- scratch (device globals; allocation-free per harness rules) -----------
__device__ __align__(16) float  g_T[(size_t)N_NODES * C];   // scatter target (51.2MB)
__device__ __align__(16) __half g_x0h[(size_t)N_NODES * C]; // fp16 copy of x0 (25.6MB)
__device__ float g_ns[N_NODES];                             // x0 @ a_tgt
__device__ int   g_rowptr[N_EDGES + 1];
__device__ int   g_node[NNZ_MAX];
__device__ float g_val[NNZ_MAX];
__device__ int   g_is64;
__device__ int   g_rolemap[3];
// W^T pair-packed bf16 hi/lo: g_Wh[n*64 + kp] = {W[2kp][n], W[2kp+1][n]}
__device__ __align__(16) unsigned g_Wh[C * C / 2];
__device__ __align__(16) unsigned g_Wl[C * C / 2];

// ---- detect dtype (int32 vs int64) and buffer roles on-device --------------
__global__ void detect_kernel(const unsigned* __restrict__ b0,
                              const unsigned* __restrict__ b1,
                              const unsigned* __restrict__ b2, int nnz) {
    __shared__ int s_float[3], s_oddzero[3], s_sorted[3], s_is64;
    __shared__ unsigned s_vals[3][64];
    int t = threadIdx.x;
    int b = t >> 6, k = t & 63;
    const unsigned* bufs[3] = {b0, b1, b2};
    if (t < 3) { s_float[t] = 1; s_oddzero[t] = 1; s_sorted[t] = 1; }
    __syncthreads();

    const unsigned* p = bufs[b];
    unsigned q = (unsigned)(((long long)k * (nnz - 2)) / 63);
    unsigned w_even = p[q & ~1u];
    unsigned w_odd  = p[q | 1u];
    if (w_even <= 0x01000000u) atomicAnd(&s_float[b], 0);
    if (w_odd != 0u)           atomicAnd(&s_oddzero[b], 0);
    __syncthreads();

    if (t == 0) {
        int is64 = 1;
        for (int i = 0; i < 3; ++i)
            if (!s_float[i] && !s_oddzero[i]) is64 = 0;
        s_is64 = is64;
    }
    __syncthreads();

    if (!s_float[b]) {
        long long e = ((long long)k * (nnz - 1)) / 63;
        s_vals[b][k] = s_is64 ? p[2 * e] : p[e];
    }
    __syncthreads();
    if (!s_float[b] && k < 63)
        if (s_vals[b][k] > s_vals[b][k + 1]) atomicAnd(&s_sorted[b], 0);
    __syncthreads();

    if (t == 0) {
        int fb = -1, eb = -1, nb = -1;
        for (int i = 0; i < 3; ++i) if (s_float[i]) fb = i;
        for (int i = 0; i < 3; ++i) {
            if (i == fb) continue;
            if (s_sorted[i] && eb < 0) eb = i; else nb = i;
        }
        if (fb < 0) fb = 2;
        if (eb < 0) eb = 1;
        if (nb < 0) nb = 0;
        g_rolemap[0] = nb; g_rolemap[1] = eb; g_rolemap[2] = fb;
        g_is64 = s_is64;
    }
}

// ---- normalize inputs, rowptr boundary-fill, zero g_T, wprep (fused) --------
__global__ void convert_kernel(const void* b0, const void* b1, const void* b2,
                               const float* __restrict__ w, int nnz) {
    int i = blockIdx.x * blockDim.x + threadIdx.x;
    {   // grid-stride zeroing of g_T (coalesced float4)
        int nt = gridDim.x * blockDim.x;
        float4* T4 = reinterpret_cast<float4*>(g_T);
        const int total4 = N_NODES * C / 4;
        for (int idx = i; idx < total4; idx += nt)
            T4[idx] = make_float4(0.f, 0.f, 0.f, 0.f);
    }
    // fused wprep: W^T pair-packed hi/lo bf16
    if (i < C * C / 2) {
        int n = i >> 6;
        int k0 = (i & 63) * 2;
        float a = w[k0 * C + n], b = w[(k0 + 1) * C + n];
        __nv_bfloat16 ah = __float2bfloat16(a), bh = __float2bfloat16(b);
        __nv_bfloat16 al = __float2bfloat16(a - __bfloat162float(ah));
        __nv_bfloat16 bl = __float2bfloat16(b - __bfloat162float(bh));
        g_Wh[i] = (unsigned)__bfloat16_as_ushort(ah) | ((unsigned)__bfloat16_as_ushort(bh) << 16);
        g_Wl[i] = (unsigned)__bfloat16_as_ushort(al) | ((unsigned)__bfloat16_as_ushort(bl) << 16);
    }
    if (i >= nnz) return;
    const void* bufs[3] = {b0, b1, b2};
    const void* pn = bufs[g_rolemap[0]];
    const void* pe = bufs[g_rolemap[1]];
    const void* pv = bufs[g_rolemap[2]];
    int is64 = g_is64;
    int n = is64 ? (int)((const long long*)pn)[i] : ((const int*)pn)[i];
    g_node[i] = min(max(n, 0), N_NODES - 1);
    g_val[i]  = ((const float*)pv)[i];

    int ec = is64 ? (int)((const long long*)pe)[i] : ((const int*)pe)[i];
    ec = min(max(ec, 0), N_EDGES - 1);
    int ep = -1;
    if (i > 0) {
        ep = is64 ? (int)((const long long*)pe)[i - 1] : ((const int*)pe)[i - 1];
        ep = min(max(ep, 0), N_EDGES - 1);
    }
    for (int t = ep + 1; t <= ec; ++t) g_rowptr[t] = i;      // lower_bound fill
    if (i == nnz - 1)
        for (int t = ec + 1; t <= N_EDGES; ++t) g_rowptr[t] = nnz;
}

// ---- node scores: x0 @ a_tgt; ALSO emits fp16 copy of x0 --------------------
__global__ void node_scores_kernel(const float* __restrict__ x0,
                                   const float* __restrict__ att) {
    int w = (blockIdx.x * blockDim.x + threadIdx.x) >> 5;
    int lane = threadIdx.x & 31;
    if (w >= N_NODES) return;
    float4 a = *reinterpret_cast<const float4*>(att + C + lane * 4);
    float4 x = *reinterpret_cast<const float4*>(x0 + (size_t)w * C + lane * 4);

    __half2 h01 = __floats2half2_rn(x.x, x.y);
    __half2 h23 = __floats2half2_rn(x.z, x.w);
    uint2 hv;
    hv.x = *reinterpret_cast<unsigned*>(&h01);
    hv.y = *reinterpret_cast<unsigned*>(&h23);
    *reinterpret_cast<uint2*>(g_x0h + (size_t)w * C + lane * 4) = hv;

    float p = x.x * a.x + x.y * a.y + x.z * a.z + x.w * a.w;
    #pragma unroll
    for (int o = 16; o; o >>= 1) p += __shfl_xor_sync(0xffffffffu, p, o);
    if (lane == 0) g_ns[w] = p;
}

// ---- fused per-edge: lane-parallel metadata + fp16 gather + red.v4 scatter --
// Chunked: each lane loads one (node,val) of the segment coalesced; inner loop
// shuffles. Scores for up to 32 nnz computed in ONE parallel ELU pass.
__global__ void edge_fused_kernel(const float* __restrict__ att) {
    int w = (blockIdx.x * blockDim.x + threadIdx.x) >> 5;
    int lane = threadIdx.x & 31;
    if (w >= N_EDGES) return;
    int lo = g_rowptr[w];
    int hi = g_rowptr[w + 1];
    if (lo == hi) return;

    const unsigned FULL = 0xffffffffu;

    // ---- Phase A: gather m = sum v_i * x0h[n_i] ----
    float4 acc = make_float4(0.f, 0.f, 0.f, 0.f);
    for (int base = lo; base < hi; base += 32) {
        int idx = base + lane;
        int   nl = (idx < hi) ? g_node[idx] : 0;
        float vl = (idx < hi) ? g_val[idx] : 0.f;
        int m = min(32, hi - base);
        for (int j = 0; j < m; ++j) {
            int   n = __shfl_sync(FULL, nl, j);
            float v = __shfl_sync(FULL, vl, j);
            uint2 hv = *reinterpret_cast<const uint2*>(g_x0h + (size_t)n * C + lane * 4);
            float2 f01 = __half22float2(*reinterpret_cast<__half2*>(&hv.x));
            float2 f23 = __half22float2(*reinterpret_cast<__half2*>(&hv.y));
            acc.x = fmaf(v, f01.x, acc.x);
            acc.y = fmaf(v, f01.y, acc.y);
            acc.z = fmaf(v, f23.x, acc.z);
            acc.w = fmaf(v, f23.y, acc.w);
        }
    }

    float4 asrc = *reinterpret_cast<const float4*>(att + lane * 4);
    float es = acc.x * asrc.x + acc.y * asrc.y + acc.z * asrc.z + acc.w * asrc.w;
    #pragma unroll
    for (int o = 16; o; o >>= 1) es += __shfl_xor_sync(FULL, es, o);

    // ---- Phase B: lane-parallel scores, then red.v4 scatter ----
    for (int base = lo; base < hi; base += 32) {
        int idx = base + lane;
        bool valid = idx < hi;
        int   nl = valid ? g_node[idx] : 0;
        float vl = valid ? g_val[idx] : 0.f;
        float nsl = valid ? g_ns[nl] : 0.f;
        float sl = es + nsl;
        float scl = (sl > 0.f ? sl : expm1f(sl)) * vl;   // 32 scores in parallel
        int m = min(32, hi - base);
        for (int j = 0; j < m; ++j) {
            int   n  = __shfl_sync(FULL, nl, j);
            float sc = __shfl_sync(FULL, scl, j);
            float* dst = g_T + (size_t)n * C + lane * 4;
            asm volatile("red.global.add.v4.f32 [%0], {%1,%2,%3,%4};"
                         :: "l"(dst), "f"(sc * acc.x), "f"(sc * acc.y),
                            "f"(sc * acc.z), "f"(sc * acc.w)
                         : "memory");
        }
    }
}

// ============== out = T @ W via mma.sync bf16 3-split (base sm_103) ==========
__device__ __forceinline__ void mma_bf16(float* c, const unsigned* a, const unsigned* b) {
    asm volatile(
        "mma.sync.aligned.m16n8k16.row.col.f32.bf16.bf16.f32 "
        "{%0,%1,%2,%3}, {%4,%5,%6,%7}, {%8,%9}, {%0,%1,%2,%3};"
        : "+f"(c[0]), "+f"(c[1]), "+f"(c[2]), "+f"(c[3])
        : "r"(a[0]), "r"(a[1]), "r"(a[2]), "r"(a[3]), "r"(b[0]), "r"(b[1]));
}

#define STR 68   // pair-words per row in smem (64 + 4 pad: conflict-free frags)

__global__ void __launch_bounds__(256, 1) gemm_mma_kernel(float* __restrict__ out) {
    extern __shared__ unsigned sm[];
    unsigned* Ah = sm;                 // [128][STR]
    unsigned* Al = sm + 128 * STR;
    unsigned* Wh = sm + 2 * 128 * STR;
    unsigned* Wl = sm + 3 * 128 * STR;
    int tid = threadIdx.x, wid = tid >> 5, lane = tid & 31;
    int m0 = blockIdx.x * 128;

    #pragma unroll
    for (int j = 0; j < 32; ++j) {
        int i = tid + j * 256;
        int n = i >> 6, kp = i & 63;
        Wh[n * STR + kp] = g_Wh[i];
        Wl[n * STR + kp] = g_Wl[i];
    }
    for (int i = tid; i < C * C / 2; i += 256) {
        int r = i >> 6, kp = i & 63;
        int grow = m0 + r;
        float a = 0.f, b = 0.f;
        if (grow < N_NODES) {
            float2 v = *reinterpret_cast<const float2*>(g_T + (size_t)grow * C + kp * 2);
            a = v.x; b = v.y;
        }
        __nv_bfloat16 ah = __float2bfloat16(a), bh = __float2bfloat16(b);
        __nv_bfloat16 al = __float2bfloat16(a - __bfloat162float(ah));
        __nv_bfloat16 bl = __float2bfloat16(b - __bfloat162float(bh));
        Ah[r * STR + kp] = (unsigned)__bfloat16_as_ushort(ah) | ((unsigned)__bfloat16_as_ushort(bh) << 16);
        Al[r * STR + kp] = (unsigned)__bfloat16_as_ushort(al) | ((unsigned)__bfloat16_as_ushort(bl) << 16);
    }
    __syncthreads();

    int g = lane >> 2, t = lane & 3;
    int row = wid * 16 + g;

    float c[16][4];
    #pragma unroll
    for (int nt = 0; nt < 16; ++nt)
        c[nt][0] = c[nt][1] = c[nt][2] = c[nt][3] = 0.f;

    #pragma unroll
    for (int k0 = 0; k0 < 8; ++k0) {
        int kb = k0 * 8;
        unsigned ah[4], al[4];
        ah[0] = Ah[row * STR + kb + t];       ah[1] = Ah[(row + 8) * STR + kb + t];
        ah[2] = Ah[row * STR + kb + t + 4];   ah[3] = Ah[(row + 8) * STR + kb + t + 4];
        al[0] = Al[row * STR + kb + t];       al[1] = Al[(row + 8) * STR + kb + t];
        al[2] = Al[row * STR + kb + t + 4];   al[3] = Al[(row + 8) * STR + kb + t + 4];
        #pragma unroll
        for (int nt = 0; nt < 16; ++nt) {
            int n = nt * 8 + g;
            unsigned bh[2], bl[2];
            bh[0] = Wh[n * STR + kb + t]; bh[1] = Wh[n * STR + kb + t + 4];
            bl[0] = Wl[n * STR + kb + t]; bl[1] = Wl[n * STR + kb + t + 4];
            mma_bf16(c[nt], ah, bh);
            mma_bf16(c[nt], ah, bl);
            mma_bf16(c[nt], al, bh);
        }
    }

    int grow0 = m0 + row, grow1 = grow0 + 8;
    #pragma unroll
    for (int nt = 0; nt < 16; ++nt) {
        int col = nt * 8 + 2 * t;
        if (grow0 < N_NODES)
            *reinterpret_cast<float2*>(out + (size_t)grow0 * C + col) = make_float2(c[nt][0], c[nt][1]);
        if (grow1 < N_NODES)
            *reinterpret_cast<float2*>(out + (size_t)grow1 * C + col) = make_float2(c[nt][2], c[nt][3]);
    }
}
#define GEMM_SMEM (4 * 128 * STR * 4)   // 139264 B

// -----------------------------------------------------------------------------
extern "C" void kernel_launch(void* const* d_in, const int* in_sizes, int n_in,
                              void* d_out, int out_size) {
    const float* x0 = nullptr; const float* weight = nullptr; const float* att = nullptr;
    const void* big[3] = {nullptr, nullptr, nullptr};
    int nnz = 0, big_seen = 0;
    for (int i = 0; i < n_in; ++i) {
        int sz = in_sizes[i];
        if (sz == N_NODES * C)      x0 = (const float*)d_in[i];
        else if (sz == C * C)       weight = (const float*)d_in[i];
        else if (sz == 2 * C)       att = (const float*)d_in[i];
        else if (big_seen < 3)      { big[big_seen++] = d_in[i]; nnz = sz; }
    }
    float* out = (float*)d_out;

    // edge_fused kept at launch slot #4 (the ncu-profiled slot).
    detect_kernel<<<1, 192>>>((const unsigned*)big[0], (const unsigned*)big[1],
                              (const unsigned*)big[2], nnz);
    convert_kernel<<<(nnz + 255) / 256, 256>>>(big[0], big[1], big[2], weight, nnz);
    node_scores_kernel<<<(N_NODES * 32 + 255) / 256, 256>>>(x0, att);
    edge_fused_kernel<<<(N_EDGES * 32 + 255) / 256, 256>>>(att);              // slot 4
    cudaFuncSetAttribute(gemm_mma_kernel,
                         cudaFuncAttributeMaxDynamicSharedMemorySize, GEMM_SMEM);
    gemm_mma_kernel<<<(N_NODES + 127) / 128, 256, GEMM_SMEM>>>(out);
}

// round 10
// speedup vs baseline: 1.8456x; 1.0107x over previous
#include <cuda_runtime.h>
#include <cuda_bf16.h>
#include <cuda_fp16.h>
#include <math.h>
#include <stdint.h>

#define N_NODES 100000
#define N_EDGES 100000
#define NNZ_MAX 1600000
#define C 128
#define SCAN_BLK 1024
#define N_SCAN_BLOCKS ((N_NODES + SCAN_BLK - 1) / SCAN_BLK)   // 98

// ---- scratch (device globals; allocation-free per harness rules) -----------
__device__ __align__(16) float  g_T[(size_t)N_NODES * C];    // node-pass output (51.2MB)
__device__ __align__(16) __half g_mh[(size_t)N_EDGES * C];   // fp16 m rows (25.6MB)
__device__ __align__(16) __half g_x0h[(size_t)N_NODES * C];  // fp16 x0 (25.6MB)
__device__ float g_ns[N_NODES];
__device__ float g_es[N_EDGES];
__device__ int   g_rowptr[N_EDGES + 1];
__device__ int   g_nodeptr[N_NODES + 1];
__device__ int   g_pos[N_NODES];
__device__ int   g_cnt[N_NODES];
__device__ int   g_bsum[N_SCAN_BLOCKS];
__device__ int   g_boff[N_SCAN_BLOCKS];
__device__ int   g_node[NNZ_MAX];
__device__ int   g_edge[NNZ_MAX];
__device__ float g_val[NNZ_MAX];
__device__ int   g_pe[NNZ_MAX];      // edge id, node-sorted
__device__ float g_pv[NNZ_MAX];      // value, node-sorted
__device__ int   g_is64;
__device__ int   g_rolemap[3];
__device__ __align__(16) unsigned g_Wh[C * C / 2];
__device__ __align__(16) unsigned g_Wl[C * C / 2];

// ---- detect dtype (int32 vs int64) and buffer roles on-device --------------
__global__ void detect_kernel(const unsigned* __restrict__ b0,
                              const unsigned* __restrict__ b1,
                              const unsigned* __restrict__ b2, int nnz) {
    __shared__ int s_float[3], s_oddzero[3], s_sorted[3], s_is64;
    __shared__ unsigned s_vals[3][64];
    int t = threadIdx.x;
    int b = t >> 6, k = t & 63;
    const unsigned* bufs[3] = {b0, b1, b2};
    if (t < 3) { s_float[t] = 1; s_oddzero[t] = 1; s_sorted[t] = 1; }
    __syncthreads();

    const unsigned* p = bufs[b];
    unsigned q = (unsigned)(((long long)k * (nnz - 2)) / 63);
    unsigned w_even = p[q & ~1u];
    unsigned w_odd  = p[q | 1u];
    if (w_even <= 0x01000000u) atomicAnd(&s_float[b], 0);
    if (w_odd != 0u)           atomicAnd(&s_oddzero[b], 0);
    __syncthreads();

    if (t == 0) {
        int is64 = 1;
        for (int i = 0; i < 3; ++i)
            if (!s_float[i] && !s_oddzero[i]) is64 = 0;
        s_is64 = is64;
    }
    __syncthreads();

    if (!s_float[b]) {
        long long e = ((long long)k * (nnz - 1)) / 63;
        s_vals[b][k] = s_is64 ? p[2 * e] : p[e];
    }
    __syncthreads();
    if (!s_float[b] && k < 63)
        if (s_vals[b][k] > s_vals[b][k + 1]) atomicAnd(&s_sorted[b], 0);
    __syncthreads();

    if (t == 0) {
        int fb = -1, eb = -1, nb = -1;
        for (int i = 0; i < 3; ++i) if (s_float[i]) fb = i;
        for (int i = 0; i < 3; ++i) {
            if (i == fb) continue;
            if (s_sorted[i] && eb < 0) eb = i; else nb = i;
        }
        if (fb < 0) fb = 2;
        if (eb < 0) eb = 1;
        if (nb < 0) nb = 0;
        g_rolemap[0] = nb; g_rolemap[1] = eb; g_rolemap[2] = fb;
        g_is64 = s_is64;
    }
}

// -------------------------------------------------------------- zero cnt ----
__global__ void zero_cnt_kernel() {
    int i = blockIdx.x * blockDim.x + threadIdx.x;
    if (i < N_NODES) g_cnt[i] = 0;
}

// ---- normalize, rowptr boundary-fill, node histogram, wprep (fused) ---------
__global__ void convert_kernel(const void* b0, const void* b1, const void* b2,
                               const float* __restrict__ w, int nnz) {
    int i = blockIdx.x * blockDim.x + threadIdx.x;
    if (i < C * C / 2) {          // fused wprep: W^T pair-packed hi/lo bf16
        int n = i >> 6;
        int k0 = (i & 63) * 2;
        float a = w[k0 * C + n], b = w[(k0 + 1) * C + n];
        __nv_bfloat16 ah = __float2bfloat16(a), bh = __float2bfloat16(b);
        __nv_bfloat16 al = __float2bfloat16(a - __bfloat162float(ah));
        __nv_bfloat16 bl = __float2bfloat16(b - __bfloat162float(bh));
        g_Wh[i] = (unsigned)__bfloat16_as_ushort(ah) | ((unsigned)__bfloat16_as_ushort(bh) << 16);
        g_Wl[i] = (unsigned)__bfloat16_as_ushort(al) | ((unsigned)__bfloat16_as_ushort(bl) << 16);
    }
    if (i >= nnz) return;
    const void* bufs[3] = {b0, b1, b2};
    const void* pn = bufs[g_rolemap[0]];
    const void* pe = bufs[g_rolemap[1]];
    const void* pv = bufs[g_rolemap[2]];
    int is64 = g_is64;
    int n = is64 ? (int)((const long long*)pn)[i] : ((const int*)pn)[i];
    n = min(max(n, 0), N_NODES - 1);
    g_node[i] = n;
    g_val[i]  = ((const float*)pv)[i];
    atomicAdd(&g_cnt[n], 1);

    int ec = is64 ? (int)((const long long*)pe)[i] : ((const int*)pe)[i];
    ec = min(max(ec, 0), N_EDGES - 1);
    g_edge[i] = ec;
    int ep = -1;
    if (i > 0) {
        ep = is64 ? (int)((const long long*)pe)[i - 1] : ((const int*)pe)[i - 1];
        ep = min(max(ep, 0), N_EDGES - 1);
    }
    for (int t = ep + 1; t <= ec; ++t) g_rowptr[t] = i;
    if (i == nnz - 1)
        for (int t = ec + 1; t <= N_EDGES; ++t) g_rowptr[t] = nnz;
}

// ---- node scores: x0 @ a_tgt; ALSO emits fp16 copy of x0 --------------------
__global__ void node_scores_kernel(const float* __restrict__ x0,
                                   const float* __restrict__ att) {
    int w = (blockIdx.x * blockDim.x + threadIdx.x) >> 5;
    int lane = threadIdx.x & 31;
    if (w >= N_NODES) return;
    float4 a = *reinterpret_cast<const float4*>(att + C + lane * 4);
    float4 x = *reinterpret_cast<const float4*>(x0 + (size_t)w * C + lane * 4);

    __half2 h01 = __floats2half2_rn(x.x, x.y);
    __half2 h23 = __floats2half2_rn(x.z, x.w);
    uint2 hv;
    hv.x = *reinterpret_cast<unsigned*>(&h01);
    hv.y = *reinterpret_cast<unsigned*>(&h23);
    *reinterpret_cast<uint2*>(g_x0h + (size_t)w * C + lane * 4) = hv;

    float p = x.x * a.x + x.y * a.y + x.z * a.z + x.w * a.w;
    #pragma unroll
    for (int o = 16; o; o >>= 1) p += __shfl_xor_sync(0xffffffffu, p, o);
    if (lane == 0) g_ns[w] = p;
}

// ---- edge pass: gather x0h, m in fp32 regs -> store fp16 m row + es ---------
__global__ void edge_pass_kernel(const float* __restrict__ att) {
    int w = (blockIdx.x * blockDim.x + threadIdx.x) >> 5;
    int lane = threadIdx.x & 31;
    if (w >= N_EDGES) return;
    int lo = g_rowptr[w];
    int hi = g_rowptr[w + 1];
    if (lo == hi) return;             // such edges never appear in g_pe

    const unsigned FULL = 0xffffffffu;
    float4 acc = make_float4(0.f, 0.f, 0.f, 0.f);
    for (int base = lo; base < hi; base += 32) {
        int idx = base + lane;
        int   nl = (idx < hi) ? g_node[idx] : 0;
        float vl = (idx < hi) ? g_val[idx] : 0.f;
        int m = min(32, hi - base);
        for (int j = 0; j < m; ++j) {
            int   n = __shfl_sync(FULL, nl, j);
            float v = __shfl_sync(FULL, vl, j);
            uint2 hv = *reinterpret_cast<const uint2*>(g_x0h + (size_t)n * C + lane * 4);
            float2 f01 = __half22float2(*reinterpret_cast<__half2*>(&hv.x));
            float2 f23 = __half22float2(*reinterpret_cast<__half2*>(&hv.y));
            acc.x = fmaf(v, f01.x, acc.x);
            acc.y = fmaf(v, f01.y, acc.y);
            acc.z = fmaf(v, f23.x, acc.z);
            acc.w = fmaf(v, f23.y, acc.w);
        }
    }

    float4 asrc = *reinterpret_cast<const float4*>(att + lane * 4);
    float es = acc.x * asrc.x + acc.y * asrc.y + acc.z * asrc.z + acc.w * asrc.w;
    #pragma unroll
    for (int o = 16; o; o >>= 1) es += __shfl_xor_sync(FULL, es, o);

    __half2 h01 = __floats2half2_rn(acc.x, acc.y);
    __half2 h23 = __floats2half2_rn(acc.z, acc.w);
    uint2 hv;
    hv.x = *reinterpret_cast<unsigned*>(&h01);
    hv.y = *reinterpret_cast<unsigned*>(&h23);
    *reinterpret_cast<uint2*>(g_mh + (size_t)w * C + lane * 4) = hv;
    if (lane == 0) g_es[w] = es;
}

// ---- multi-block exclusive scan of g_cnt -> g_nodeptr/g_pos -----------------
__global__ void scan_reduce_kernel() {
    __shared__ int s[32];
    int i = blockIdx.x * SCAN_BLK + threadIdx.x;
    int v = (i < N_NODES) ? g_cnt[i] : 0;
    int lane = threadIdx.x & 31, wid = threadIdx.x >> 5;
    #pragma unroll
    for (int o = 16; o; o >>= 1) v += __shfl_xor_sync(0xffffffffu, v, o);
    if (lane == 0) s[wid] = v;
    __syncthreads();
    if (wid == 0) {
        int u = s[lane];
        #pragma unroll
        for (int o = 16; o; o >>= 1) u += __shfl_xor_sync(0xffffffffu, u, o);
        if (lane == 0) g_bsum[blockIdx.x] = u;
    }
}

__global__ void scan_top_kernel() {     // 128 threads: exclusive scan of 98 sums
    __shared__ int s[4];
    int t = threadIdx.x;
    int v = (t < N_SCAN_BLOCKS) ? g_bsum[t] : 0;
    int lane = t & 31, wid = t >> 5;
    int incl = v;
    #pragma unroll
    for (int o = 1; o < 32; o <<= 1) {
        int u = __shfl_up_sync(0xffffffffu, incl, o);
        if (lane >= o) incl += u;
    }
    if (lane == 31) s[wid] = incl;
    __syncthreads();
    int add = 0;
    for (int k = 0; k < wid; ++k) add += s[k];
    if (t < N_SCAN_BLOCKS) g_boff[t] = incl + add - v;
}

__global__ void scan_apply_kernel(int nnz) {
    __shared__ int s[32];
    int b = blockIdx.x;
    int i = b * SCAN_BLK + threadIdx.x;
    int v = (i < N_NODES) ? g_cnt[i] : 0;
    int lane = threadIdx.x & 31, wid = threadIdx.x >> 5;
    int incl = v;
    #pragma unroll
    for (int o = 1; o < 32; o <<= 1) {
        int u = __shfl_up_sync(0xffffffffu, incl, o);
        if (lane >= o) incl += u;
    }
    if (lane == 31) s[wid] = incl;
    __syncthreads();
    if (wid == 0) {
        int u = s[lane];
        #pragma unroll
        for (int o = 1; o < 32; o <<= 1) {
            int x = __shfl_up_sync(0xffffffffu, u, o);
            if (lane >= o) u += x;
        }
        s[lane] = u;
    }
    __syncthreads();
    int excl = incl - v + (wid > 0 ? s[wid - 1] : 0) + g_boff[b];
    if (i < N_NODES) { g_nodeptr[i] = excl; g_pos[i] = excl; }
    if (b == 0 && threadIdx.x == 0) g_nodeptr[N_NODES] = nnz;
}

// ---- scatter nnz into node-sorted order (int atomics, spread) ---------------
__global__ void sort_scatter_kernel(int nnz) {
    int i = blockIdx.x * blockDim.x + threadIdx.x;
    if (i >= nnz) return;
    int n = g_node[i];
    int j = atomicAdd(&g_pos[n], 1);
    g_pe[j] = g_edge[i];
    g_pv[j] = g_val[i];
}

// ---- node pass: lane-parallel scores + fp16 m gather -> fp32 T row store ----
__global__ void node_pass_kernel() {
    int w = (blockIdx.x * blockDim.x + threadIdx.x) >> 5;
    int lane = threadIdx.x & 31;
    if (w >= N_NODES) return;
    int lo = g_nodeptr[w];
    int hi = g_nodeptr[w + 1];
    float ns = g_ns[w];

    const unsigned FULL = 0xffffffffu;
    float4 acc = make_float4(0.f, 0.f, 0.f, 0.f);
    for (int base = lo; base < hi; base += 32) {
        int idx = base + lane;
        bool valid = idx < hi;
        int   el = valid ? g_pe[idx] : 0;
        float vl = valid ? g_pv[idx] : 0.f;
        float esl = valid ? g_es[el] : 0.f;
        float sl = esl + ns;
        float scl = (sl > 0.f ? sl : expm1f(sl)) * vl;
        int m = min(32, hi - base);
        for (int j = 0; j < m; ++j) {
            int   e  = __shfl_sync(FULL, el, j);
            float sc = __shfl_sync(FULL, scl, j);
            uint2 hv = *reinterpret_cast<const uint2*>(g_mh + (size_t)e * C + lane * 4);
            float2 f01 = __half22float2(*reinterpret_cast<__half2*>(&hv.x));
            float2 f23 = __half22float2(*reinterpret_cast<__half2*>(&hv.y));
            acc.x = fmaf(sc, f01.x, acc.x);
            acc.y = fmaf(sc, f01.y, acc.y);
            acc.z = fmaf(sc, f23.x, acc.z);
            acc.w = fmaf(sc, f23.y, acc.w);
        }
    }
    *reinterpret_cast<float4*>(g_T + (size_t)w * C + lane * 4) = acc;   // always write
}

// ============== out = T @ W via mma.sync bf16 3-split (base sm_103) ==========
__device__ __forceinline__ void mma_bf16(float* c, const unsigned* a, const unsigned* b) {
    asm volatile(
        "mma.sync.aligned.m16n8k16.row.col.f32.bf16.bf16.f32 "
        "{%0,%1,%2,%3}, {%4,%5,%6,%7}, {%8,%9}, {%0,%1,%2,%3};"
        : "+f"(c[0]), "+f"(c[1]), "+f"(c[2]), "+f"(c[3])
        : "r"(a[0]), "r"(a[1]), "r"(a[2]), "r"(a[3]), "r"(b[0]), "r"(b[1]));
}

#define STR 68

__global__ void __launch_bounds__(256, 1) gemm_mma_kernel(float* __restrict__ out) {
    extern __shared__ unsigned sm[];
    unsigned* Ah = sm;
    unsigned* Al = sm + 128 * STR;
    unsigned* Wh = sm + 2 * 128 * STR;
    unsigned* Wl = sm + 3 * 128 * STR;
    int tid = threadIdx.x, wid = tid >> 5, lane = tid & 31;
    int m0 = blockIdx.x * 128;

    #pragma unroll
    for (int j = 0; j < 32; ++j) {
        int i = tid + j * 256;
        int n = i >> 6, kp = i & 63;
        Wh[n * STR + kp] = g_Wh[i];
        Wl[n * STR + kp] = g_Wl[i];
    }
    for (int i = tid; i < C * C / 2; i += 256) {
        int r = i >> 6, kp = i & 63;
        int grow = m0 + r;
        float a = 0.f, b = 0.f;
        if (grow < N_NODES) {
            float2 v = *reinterpret_cast<const float2*>(g_T + (size_t)grow * C + kp * 2);
            a = v.x; b = v.y;
        }
        __nv_bfloat16 ah = __float2bfloat16(a), bh = __float2bfloat16(b);
        __nv_bfloat16 al = __float2bfloat16(a - __bfloat162float(ah));
        __nv_bfloat16 bl = __float2bfloat16(b - __bfloat162float(bh));
        Ah[r * STR + kp] = (unsigned)__bfloat16_as_ushort(ah) | ((unsigned)__bfloat16_as_ushort(bh) << 16);
        Al[r * STR + kp] = (unsigned)__bfloat16_as_ushort(al) | ((unsigned)__bfloat16_as_ushort(bl) << 16);
    }
    __syncthreads();

    int g = lane >> 2, t = lane & 3;
    int row = wid * 16 + g;

    float c[16][4];
    #pragma unroll
    for (int nt = 0; nt < 16; ++nt)
        c[nt][0] = c[nt][1] = c[nt][2] = c[nt][3] = 0.f;

    #pragma unroll
    for (int k0 = 0; k0 < 8; ++k0) {
        int kb = k0 * 8;
        unsigned ah[4], al[4];
        ah[0] = Ah[row * STR + kb + t];       ah[1] = Ah[(row + 8) * STR + kb + t];
        ah[2] = Ah[row * STR + kb + t + 4];   ah[3] = Ah[(row + 8) * STR + kb + t + 4];
        al[0] = Al[row * STR + kb + t];       al[1] = Al[(row + 8) * STR + kb + t];
        al[2] = Al[row * STR + kb + t + 4];   al[3] = Al[(row + 8) * STR + kb + t + 4];
        #pragma unroll
        for (int nt = 0; nt < 16; ++nt) {
            int n = nt * 8 + g;
            unsigned bh[2], bl[2];
            bh[0] = Wh[n * STR + kb + t]; bh[1] = Wh[n * STR + kb + t + 4];
            bl[0] = Wl[n * STR + kb + t]; bl[1] = Wl[n * STR + kb + t + 4];
            mma_bf16(c[nt], ah, bh);
            mma_bf16(c[nt], ah, bl);
            mma_bf16(c[nt], al, bh);
        }
    }

    int grow0 = m0 + row, grow1 = grow0 + 8;
    #pragma unroll
    for (int nt = 0; nt < 16; ++nt) {
        int col = nt * 8 + 2 * t;
        if (grow0 < N_NODES)
            *reinterpret_cast<float2*>(out + (size_t)grow0 * C + col) = make_float2(c[nt][0], c[nt][1]);
        if (grow1 < N_NODES)
            *reinterpret_cast<float2*>(out + (size_t)grow1 * C + col) = make_float2(c[nt][2], c[nt][3]);
    }
}
#define GEMM_SMEM (4 * 128 * STR * 4)

// -----------------------------------------------------------------------------
extern "C" void kernel_launch(void* const* d_in, const int* in_sizes, int n_in,
                              void* d_out, int out_size) {
    const float* x0 = nullptr; const float* weight = nullptr; const float* att = nullptr;
    const void* big[3] = {nullptr, nullptr, nullptr};
    int nnz = 0, big_seen = 0;
    for (int i = 0; i < n_in; ++i) {
        int sz = in_sizes[i];
        if (sz == N_NODES * C)      x0 = (const float*)d_in[i];
        else if (sz == C * C)       weight = (const float*)d_in[i];
        else if (sz == 2 * C)       att = (const float*)d_in[i];
        else if (big_seen < 3)      { big[big_seen++] = d_in[i]; nnz = sz; }
    }
    float* out = (float*)d_out;

    detect_kernel<<<1, 192>>>((const unsigned*)big[0], (const unsigned*)big[1],
                              (const unsigned*)big[2], nnz);
    zero_cnt_kernel<<<(N_NODES + 255) / 256, 256>>>();
    convert_kernel<<<(nnz + 255) / 256, 256>>>(big[0], big[1], big[2], weight, nnz);
    node_scores_kernel<<<(N_NODES * 32 + 255) / 256, 256>>>(x0, att);
    edge_pass_kernel<<<(N_EDGES * 32 + 255) / 256, 256>>>(att);
    scan_reduce_kernel<<<N_SCAN_BLOCKS, SCAN_BLK>>>();
    scan_top_kernel<<<1, 128>>>();
    scan_apply_kernel<<<N_SCAN_BLOCKS, SCAN_BLK>>>(nnz);
    sort_scatter_kernel<<<(nnz + 255) / 256, 256>>>(nnz);
    node_pass_kernel<<<(N_NODES * 32 + 255) / 256, 256>>>();

    cudaFuncSetAttribute(gemm_mma_kernel,
                         cudaFuncAttributeMaxDynamicSharedMemorySize, GEMM_SMEM);
    gemm_mma_kernel<<<(N_NODES + 127) / 128, 256, GEMM_SMEM>>>(out);
}